// round 1
// baseline (speedup 1.0000x reference)
#include <cuda_runtime.h>
#include <cstdint>

#define N_NODES 100000
#define N_EDGES 25000
#define N_INC   600000
#define D       128
#define ATTR_FLOATS (25000*32)

// ---------------- scratch (no allocations allowed) ----------------
__device__ float g_y [N_NODES*D];     // GEMM output (X @ W)
__device__ float g_h [N_NODES*D];     // node features between layers
__device__ float g_ef[N_EDGES*D];     // hyperedge features
__device__ int   g_cnt_e[N_EDGES];
__device__ int   g_cnt_n[N_NODES];
__device__ int   g_off_e[N_EDGES+1];
__device__ int   g_off_n[N_NODES+1];
__device__ int   g_cur_e[N_EDGES];
__device__ int   g_cur_n[N_NODES];
__device__ int   g_csr_e[N_INC];      // node ids grouped by edge
__device__ int   g_csr_n[N_INC];      // edge ids grouped by node
__device__ float g_binv[N_EDGES];
__device__ float g_dinv[N_NODES];
__device__ int   g_bsums[1024];

// ---------------- helpers ----------------
__device__ __forceinline__ void ffma2(unsigned long long &d,
                                      unsigned long long a,
                                      unsigned long long b) {
    asm("fma.rn.f32x2 %0, %1, %2, %0;" : "+l"(d) : "l"(a), "l"(b));
}
__device__ __forceinline__ unsigned long long dupf(float f) {
    unsigned u = __float_as_uint(f);
    return ((unsigned long long)u << 32) | (unsigned long long)u;
}
__device__ __forceinline__ float lo32(unsigned long long v) {
    return __uint_as_float((unsigned)v);
}
__device__ __forceinline__ float hi32(unsigned long long v) {
    return __uint_as_float((unsigned)(v >> 32));
}

// ---------------- CSR build ----------------
__global__ void k_zero() {
    int i = blockIdx.x * blockDim.x + threadIdx.x;
    if (i < N_EDGES) { g_cnt_e[i] = 0; g_cur_e[i] = 0; }
    if (i < N_NODES) { g_cnt_n[i] = 0; g_cur_n[i] = 0; }
}

__global__ void k_count(const int* __restrict__ ni, const int* __restrict__ ei) {
    int i = blockIdx.x * blockDim.x + threadIdx.x;
    if (i < N_INC) {
        atomicAdd(&g_cnt_e[ei[i]], 1);
        atomicAdd(&g_cnt_n[ni[i]], 1);
    }
}

__device__ __forceinline__ int blockScanInc(int v, int* ws) {
    int lane = threadIdx.x & 31, wid = threadIdx.x >> 5;
    #pragma unroll
    for (int o = 1; o < 32; o <<= 1) {
        int n = __shfl_up_sync(0xffffffffu, v, o);
        if (lane >= o) v += n;
    }
    if (lane == 31) ws[wid] = v;
    __syncthreads();
    if (wid == 0) {
        int nw = blockDim.x >> 5;
        int s = (lane < nw) ? ws[lane] : 0;
        #pragma unroll
        for (int o = 1; o < 32; o <<= 1) {
            int n = __shfl_up_sync(0xffffffffu, s, o);
            if (lane >= o) s += n;
        }
        ws[lane] = s;
    }
    __syncthreads();
    if (wid > 0) v += ws[wid - 1];
    return v;
}

// which==0 -> edges (cnt_e -> off_e), which==1 -> nodes (cnt_n -> off_n)
__global__ void k_scan1(int which, int n) {
    __shared__ int ws[32];
    const int* in = which ? g_cnt_n : g_cnt_e;
    int*      out = which ? g_off_n : g_off_e;
    int i = blockIdx.x * 1024 + threadIdx.x;
    int v = (i < n) ? in[i] : 0;
    int inc = blockScanInc(v, ws);
    if (i < n) out[i] = inc - v;
    if (threadIdx.x == 1023) g_bsums[blockIdx.x] = inc;
}

__global__ void k_scan2(int nb) {
    __shared__ int ws[32];
    int v = (threadIdx.x < nb) ? g_bsums[threadIdx.x] : 0;
    int inc = blockScanInc(v, ws);
    if (threadIdx.x < nb) g_bsums[threadIdx.x] = inc - v;  // exclusive
}

__global__ void k_scan3(int which, int n) {
    int* out = which ? g_off_n : g_off_e;
    int i = blockIdx.x * 1024 + threadIdx.x;
    if (i < n) out[i] += g_bsums[blockIdx.x];
    if (i == 0) out[n] = N_INC;
}

__global__ void k_inv() {
    int i = blockIdx.x * blockDim.x + threadIdx.x;
    if (i < N_EDGES) g_binv[i] = (g_cnt_e[i] > 0) ? (1.0f / (float)g_cnt_e[i]) : 0.0f;
    if (i < N_NODES) g_dinv[i] = (g_cnt_n[i] > 0) ? (1.0f / (float)g_cnt_n[i]) : 0.0f;
}

__global__ void k_fill(const int* __restrict__ ni, const int* __restrict__ ei) {
    int i = blockIdx.x * blockDim.x + threadIdx.x;
    if (i < N_INC) {
        int e = ei[i], n = ni[i];
        int pe = atomicAdd(&g_cur_e[e], 1);
        g_csr_e[g_off_e[e] + pe] = n;
        int pn = atomicAdd(&g_cur_n[n], 1);
        g_csr_n[g_off_n[n] + pn] = e;
    }
}

// ---------------- GEMM: g_y = A[100000x128] @ W[128x128]  (fp32 via f32x2) ----
// Tile 128 rows x 128 cols, 256 threads, each thread 8 rows x 8 cols.
// Accumulators pack (row 2r, row 2r+1) per column in one f32x2 register.
// A tile stored k-major (As[kk][m]) -> per-thread row octet is contiguous.
// B tile stored value-duplicated (Bs[kk][n] = (w,w)) -> no pack instructions.
__global__ void __launch_bounds__(256, 2)
k_gemm(const float* __restrict__ Ain, const float* __restrict__ W) {
    const float* A = Ain ? Ain : g_h;
    __shared__ float As[2][8][132];                 // pitch 132 avoids STS conflicts
    __shared__ unsigned long long Bs[2][8][128];

    const int tid = threadIdx.x;
    const int m0  = blockIdx.x * 128;
    const int tx = tid & 15, ty = tid >> 4;
    const int r0 = ty * 8, c0 = tx * 8;
    const int lr = tid >> 1;            // 0..127  (A-tile load row)
    const int lc = (tid & 1) * 4;       // 0 or 4  (A-tile load k offset)
    const int bk = tid >> 5;            // 0..7    (B-tile load k)
    const int bn = (tid & 31) * 4;      // 0..124  (B-tile load n)

    unsigned long long acc[4][8];
    #pragma unroll
    for (int r = 0; r < 4; r++)
        #pragma unroll
        for (int j = 0; j < 8; j++) acc[r][j] = 0ull;

    auto loadStage = [&](int k0, int buf) {
        float4 av = make_float4(0.f, 0.f, 0.f, 0.f);
        int row = m0 + lr;
        if (row < N_NODES)
            av = *(const float4*)&A[(size_t)row * D + k0 + lc];
        As[buf][lc + 0][lr] = av.x;
        As[buf][lc + 1][lr] = av.y;
        As[buf][lc + 2][lr] = av.z;
        As[buf][lc + 3][lr] = av.w;
        float4 wv = *(const float4*)&W[(size_t)(k0 + bk) * D + bn];
        Bs[buf][bk][bn + 0] = dupf(wv.x);
        Bs[buf][bk][bn + 1] = dupf(wv.y);
        Bs[buf][bk][bn + 2] = dupf(wv.z);
        Bs[buf][bk][bn + 3] = dupf(wv.w);
    };

    loadStage(0, 0);
    __syncthreads();

    for (int k0 = 0; k0 < 128; k0 += 8) {
        int buf = (k0 >> 3) & 1;
        if (k0 + 8 < 128) loadStage(k0 + 8, buf ^ 1);
        #pragma unroll
        for (int kk = 0; kk < 8; kk++) {
            const ulonglong2* ap = (const ulonglong2*)&As[buf][kk][r0];
            ulonglong2 av0 = ap[0], av1 = ap[1];
            unsigned long long a[4] = { av0.x, av0.y, av1.x, av1.y };
            const ulonglong2* bp = (const ulonglong2*)&Bs[buf][kk][c0];
            ulonglong2 bv0 = bp[0], bv1 = bp[1], bv2 = bp[2], bv3 = bp[3];
            unsigned long long b[8] = { bv0.x, bv0.y, bv1.x, bv1.y,
                                        bv2.x, bv2.y, bv3.x, bv3.y };
            #pragma unroll
            for (int r = 0; r < 4; r++)
                #pragma unroll
                for (int j = 0; j < 8; j++)
                    ffma2(acc[r][j], a[r], b[j]);
        }
        __syncthreads();
    }

    #pragma unroll
    for (int r = 0; r < 4; r++) {
        int row = m0 + r0 + 2 * r;
        if (row < N_NODES) {
            float4 v0 = make_float4(lo32(acc[r][0]), lo32(acc[r][1]),
                                    lo32(acc[r][2]), lo32(acc[r][3]));
            float4 v1 = make_float4(lo32(acc[r][4]), lo32(acc[r][5]),
                                    lo32(acc[r][6]), lo32(acc[r][7]));
            *(float4*)&g_y[(size_t)row * D + c0]     = v0;
            *(float4*)&g_y[(size_t)row * D + c0 + 4] = v1;
        }
        if (row + 1 < N_NODES) {
            float4 v0 = make_float4(hi32(acc[r][0]), hi32(acc[r][1]),
                                    hi32(acc[r][2]), hi32(acc[r][3]));
            float4 v1 = make_float4(hi32(acc[r][4]), hi32(acc[r][5]),
                                    hi32(acc[r][6]), hi32(acc[r][7]));
            *(float4*)&g_y[(size_t)(row + 1) * D + c0]     = v0;
            *(float4*)&g_y[(size_t)(row + 1) * D + c0 + 4] = v1;
        }
    }
}

// ---------------- nodes -> hyperedges gather (warp per edge) ----------------
__global__ void k_edge_gather() {
    int w = (blockIdx.x * blockDim.x + threadIdx.x) >> 5;
    int lane = threadIdx.x & 31;
    if (w >= N_EDGES) return;
    int s = g_off_e[w], t = g_off_e[w + 1];
    float4 acc = make_float4(0.f, 0.f, 0.f, 0.f);
    for (int base = s; base < t; base += 32) {
        int rem = t - base;
        int n = (lane < rem) ? g_csr_e[base + lane] : 0;
        int cnt = rem < 32 ? rem : 32;
        for (int j = 0; j < cnt; j++) {
            int nn = __shfl_sync(0xffffffffu, n, j);
            float4 v = *(const float4*)&g_y[(size_t)nn * D + lane * 4];
            acc.x += v.x; acc.y += v.y; acc.z += v.z; acc.w += v.w;
        }
    }
    float bi = g_binv[w];
    acc.x *= bi; acc.y *= bi; acc.z *= bi; acc.w *= bi;
    *(float4*)&g_ef[(size_t)w * D + lane * 4] = acc;
}

// ---------------- hyperedges -> nodes gather + bias (+relu) ----------------
__global__ void k_node_gather(float* __restrict__ outp,
                              const float* __restrict__ b, int doRelu) {
    int w = (blockIdx.x * blockDim.x + threadIdx.x) >> 5;
    int lane = threadIdx.x & 31;
    if (w >= N_NODES) return;
    float* out = outp ? outp : g_h;
    int s = g_off_n[w], t = g_off_n[w + 1];
    float4 acc = make_float4(0.f, 0.f, 0.f, 0.f);
    for (int base = s; base < t; base += 32) {
        int rem = t - base;
        int e = (lane < rem) ? g_csr_n[base + lane] : 0;
        int cnt = rem < 32 ? rem : 32;
        for (int j = 0; j < cnt; j++) {
            int ee = __shfl_sync(0xffffffffu, e, j);
            float4 v = *(const float4*)&g_ef[(size_t)ee * D + lane * 4];
            acc.x += v.x; acc.y += v.y; acc.z += v.z; acc.w += v.w;
        }
    }
    float di = g_dinv[w];
    float4 bv = ((const float4*)b)[lane];
    float4 r;
    r.x = acc.x * di + bv.x;
    r.y = acc.y * di + bv.y;
    r.z = acc.z * di + bv.z;
    r.w = acc.w * di + bv.w;
    if (doRelu) {
        r.x = fmaxf(r.x, 0.f); r.y = fmaxf(r.y, 0.f);
        r.z = fmaxf(r.z, 0.f); r.w = fmaxf(r.w, 0.f);
    }
    *(float4*)&out[(size_t)w * D + lane * 4] = r;
}

// ---------------- attr passthrough ----------------
__global__ void k_copy_attr(const float4* __restrict__ in, float4* __restrict__ out) {
    int i = blockIdx.x * blockDim.x + threadIdx.x;
    if (i < ATTR_FLOATS / 4) out[i] = in[i];
}

// ---------------- launch ----------------
extern "C" void kernel_launch(void* const* d_in, const int* in_sizes, int n_in,
                              void* d_out, int out_size) {
    const float* x        = (const float*)d_in[0];
    const int*   node_idx = (const int*)  d_in[1];
    const int*   edge_idx = (const int*)  d_in[2];
    const float* attr     = (const float*)d_in[3];
    const float* W1 = (const float*)d_in[4];
    const float* b1 = (const float*)d_in[5];
    const float* W2 = (const float*)d_in[6];
    const float* b2 = (const float*)d_in[7];
    const float* W3 = (const float*)d_in[8];
    const float* b3 = (const float*)d_in[9];
    float* out = (float*)d_out;

    // CSR build (once; reused by all 3 layers)
    k_zero <<<(N_NODES + 255) / 256, 256>>>();
    k_count<<<(N_INC   + 255) / 256, 256>>>(node_idx, edge_idx);

    int nb_e = (N_EDGES + 1023) / 1024;   // 25
    int nb_n = (N_NODES + 1023) / 1024;   // 98
    k_scan1<<<nb_e, 1024>>>(0, N_EDGES);
    k_scan2<<<1, 1024>>>(nb_e);
    k_scan3<<<nb_e, 1024>>>(0, N_EDGES);
    k_scan1<<<nb_n, 1024>>>(1, N_NODES);
    k_scan2<<<1, 1024>>>(nb_n);
    k_scan3<<<nb_n, 1024>>>(1, N_NODES);

    k_inv <<<(N_NODES + 255) / 256, 256>>>();
    k_fill<<<(N_INC   + 255) / 256, 256>>>(node_idx, edge_idx);

    const int gemm_grid = (N_NODES + 127) / 128;   // 782
    const int eg_grid   = (N_EDGES * 32 + 255) / 256;   // 3125
    const int ng_grid   = (N_NODES * 32 + 255) / 256;   // 12500

    // Layer 1
    k_gemm<<<gemm_grid, 256>>>(x, W1);
    k_edge_gather<<<eg_grid, 256>>>();
    k_node_gather<<<ng_grid, 256>>>(nullptr, b1, 1);
    // Layer 2
    k_gemm<<<gemm_grid, 256>>>(nullptr, W2);
    k_edge_gather<<<eg_grid, 256>>>();
    k_node_gather<<<ng_grid, 256>>>(nullptr, b2, 1);
    // Layer 3 (no relu, straight into output)
    k_gemm<<<gemm_grid, 256>>>(nullptr, W3);
    k_edge_gather<<<eg_grid, 256>>>();
    k_node_gather<<<ng_grid, 256>>>(out, b3, 0);

    // hyperedge_attr passthrough after h
    k_copy_attr<<<(ATTR_FLOATS / 4 + 255) / 256, 256>>>(
        (const float4*)attr, (float4*)(out + (size_t)N_NODES * D));
}

// round 2
// speedup vs baseline: 1.8746x; 1.8746x over previous
#include <cuda_runtime.h>
#include <cstdint>

#define N_NODES 100000
#define N_EDGES 25000
#define N_INC   600000
#define D       128
#define ATTR_FLOATS (25000*32)

typedef unsigned long long ull;

// ---------------- scratch (no allocations allowed) ----------------
__device__ float g_y [N_NODES*D];     // GEMM output (X @ W)
__device__ float g_h [N_NODES*D];     // node features between layers
__device__ float g_ef[N_EDGES*D];     // hyperedge features
__device__ int   g_cnt_e[N_EDGES];
__device__ int   g_cnt_n[N_NODES];
__device__ int   g_off_e[N_EDGES+1];
__device__ int   g_off_n[N_NODES+1];
__device__ int   g_cur_e[N_EDGES];
__device__ int   g_cur_n[N_NODES];
__device__ int   g_csr_e[N_INC];      // node ids grouped by edge
__device__ int   g_csr_n[N_INC];      // edge ids grouped by node
__device__ float g_binv[N_EDGES];
__device__ float g_dinv[N_NODES];
__device__ int   g_bsums[1024];

// ---------------- helpers ----------------
__device__ __forceinline__ void ffma2(ull &d, ull a, ull b) {
    asm("fma.rn.f32x2 %0, %1, %2, %0;" : "+l"(d) : "l"(a), "l"(b));
}
__device__ __forceinline__ ull dupf(float f) {
    unsigned u = __float_as_uint(f);
    return ((ull)u << 32) | (ull)u;
}
__device__ __forceinline__ float lo32(ull v) { return __uint_as_float((unsigned)v); }
__device__ __forceinline__ float hi32(ull v) { return __uint_as_float((unsigned)(v >> 32)); }

// ---------------- CSR build ----------------
__global__ void k_zero() {
    int i = blockIdx.x * blockDim.x + threadIdx.x;
    if (i < N_EDGES) { g_cnt_e[i] = 0; g_cur_e[i] = 0; }
    if (i < N_NODES) { g_cnt_n[i] = 0; g_cur_n[i] = 0; }
}

__global__ void k_count(const int* __restrict__ ni, const int* __restrict__ ei) {
    int i = blockIdx.x * blockDim.x + threadIdx.x;
    if (i < N_INC) {
        atomicAdd(&g_cnt_e[ei[i]], 1);
        atomicAdd(&g_cnt_n[ni[i]], 1);
    }
}

__device__ __forceinline__ int blockScanInc(int v, int* ws) {
    int lane = threadIdx.x & 31, wid = threadIdx.x >> 5;
    #pragma unroll
    for (int o = 1; o < 32; o <<= 1) {
        int n = __shfl_up_sync(0xffffffffu, v, o);
        if (lane >= o) v += n;
    }
    if (lane == 31) ws[wid] = v;
    __syncthreads();
    if (wid == 0) {
        int nw = blockDim.x >> 5;
        int s = (lane < nw) ? ws[lane] : 0;
        #pragma unroll
        for (int o = 1; o < 32; o <<= 1) {
            int n = __shfl_up_sync(0xffffffffu, s, o);
            if (lane >= o) s += n;
        }
        ws[lane] = s;
    }
    __syncthreads();
    if (wid > 0) v += ws[wid - 1];
    return v;
}

__global__ void k_scan1(int which, int n) {
    __shared__ int ws[32];
    const int* in = which ? g_cnt_n : g_cnt_e;
    int*      out = which ? g_off_n : g_off_e;
    int i = blockIdx.x * 1024 + threadIdx.x;
    int v = (i < n) ? in[i] : 0;
    int inc = blockScanInc(v, ws);
    if (i < n) out[i] = inc - v;
    if (threadIdx.x == 1023) g_bsums[blockIdx.x] = inc;
}

__global__ void k_scan2(int nb) {
    __shared__ int ws[32];
    int v = (threadIdx.x < nb) ? g_bsums[threadIdx.x] : 0;
    int inc = blockScanInc(v, ws);
    if (threadIdx.x < nb) g_bsums[threadIdx.x] = inc - v;  // exclusive
}

__global__ void k_scan3(int which, int n) {
    int* out = which ? g_off_n : g_off_e;
    int i = blockIdx.x * 1024 + threadIdx.x;
    if (i < n) out[i] += g_bsums[blockIdx.x];
    if (i == 0) out[n] = N_INC;
}

__global__ void k_inv() {
    int i = blockIdx.x * blockDim.x + threadIdx.x;
    if (i < N_EDGES) g_binv[i] = (g_cnt_e[i] > 0) ? (1.0f / (float)g_cnt_e[i]) : 0.0f;
    if (i < N_NODES) g_dinv[i] = (g_cnt_n[i] > 0) ? (1.0f / (float)g_cnt_n[i]) : 0.0f;
}

__global__ void k_fill(const int* __restrict__ ni, const int* __restrict__ ei) {
    int i = blockIdx.x * blockDim.x + threadIdx.x;
    if (i < N_INC) {
        int e = ei[i], n = ni[i];
        int pe = atomicAdd(&g_cur_e[e], 1);
        g_csr_e[g_off_e[e] + pe] = n;
        int pn = atomicAdd(&g_cur_n[n], 1);
        g_csr_n[g_off_n[n] + pn] = e;
    }
}

// ---------------- GEMM: g_y = A[100000x128] @ W[128x128]  (fp32 via f32x2) ----
// 128x128 tile, 256 threads, thread tile 8 rows x 8 cols.
// Accumulators pack ROW pairs per f32x2 (rows come free from k-major A tile).
// B tile duplicated (w,w); each thread's 8 cols split into 4 groups of 2
// (cg*32 + tx*2) so every B LDS.128 is 16 contiguous 16B chunks across the
// warp -> conflict-free. A LDS.128 at ty*16 -> broadcast, conflict-free.
__global__ void __launch_bounds__(256, 2)
k_gemm(const float* __restrict__ Ain, const float* __restrict__ W) {
    const float* A = Ain ? Ain : g_h;
    __shared__ float As[2][8][128];     // k-major: As[kk][m]
    __shared__ ull   Bs[2][8][128];     // dup'd:   Bs[kk][n] = (w,w)

    const int tid = threadIdx.x;
    const int m0  = blockIdx.x * 128;
    const int tx = tid & 15, ty = tid >> 4;
    const int lr = tid >> 1;            // 0..127  A-tile load row
    const int lc = (tid & 1) * 4;       // 0/4     A-tile load k offset
    const int bk = tid >> 5;            // 0..7    B-tile load k
    const int bn = (tid & 31) * 4;      // 0..124  B-tile load n

    ull acc[4][8];
    #pragma unroll
    for (int r = 0; r < 4; r++)
        #pragma unroll
        for (int j = 0; j < 8; j++) acc[r][j] = 0ull;

    auto loadStage = [&](int k0, int buf) {
        float4 av = make_float4(0.f, 0.f, 0.f, 0.f);
        int row = m0 + lr;
        if (row < N_NODES)
            av = *(const float4*)&A[(size_t)row * D + k0 + lc];
        As[buf][lc + 0][lr] = av.x;
        As[buf][lc + 1][lr] = av.y;
        As[buf][lc + 2][lr] = av.z;
        As[buf][lc + 3][lr] = av.w;
        float4 wv = *(const float4*)&W[(size_t)(k0 + bk) * D + bn];
        Bs[buf][bk][bn + 0] = dupf(wv.x);
        Bs[buf][bk][bn + 1] = dupf(wv.y);
        Bs[buf][bk][bn + 2] = dupf(wv.z);
        Bs[buf][bk][bn + 3] = dupf(wv.w);
    };

    loadStage(0, 0);
    __syncthreads();

    for (int k0 = 0; k0 < 128; k0 += 8) {
        int buf = (k0 >> 3) & 1;
        if (k0 + 8 < 128) loadStage(k0 + 8, buf ^ 1);
        #pragma unroll
        for (int kk = 0; kk < 8; kk++) {
            // A: rows ty*4..ty*4+3 and 64+ty*4..+3 (two 16B broadcast loads)
            ulonglong2 a0 = *(const ulonglong2*)&As[buf][kk][ty * 4];
            ulonglong2 a1 = *(const ulonglong2*)&As[buf][kk][64 + ty * 4];
            ull a[4] = { a0.x, a0.y, a1.x, a1.y };
            // B: col groups cg*32 + tx*2 (four conflict-free 16B loads)
            ulonglong2 b0 = *(const ulonglong2*)&Bs[buf][kk][      tx * 2];
            ulonglong2 b1 = *(const ulonglong2*)&Bs[buf][kk][32  + tx * 2];
            ulonglong2 b2 = *(const ulonglong2*)&Bs[buf][kk][64  + tx * 2];
            ulonglong2 b3 = *(const ulonglong2*)&Bs[buf][kk][96  + tx * 2];
            ull b[8] = { b0.x, b0.y, b1.x, b1.y, b2.x, b2.y, b3.x, b3.y };
            #pragma unroll
            for (int r = 0; r < 4; r++)
                #pragma unroll
                for (int j = 0; j < 8; j++)
                    ffma2(acc[r][j], a[r], b[j]);
        }
        __syncthreads();
    }

    // store: row pair rp -> rows base, base+1 ; col groups cg*32 + tx*2
    #pragma unroll
    for (int rp = 0; rp < 4; rp++) {
        int base = (rp < 2) ? (ty * 4 + rp * 2) : (64 + ty * 4 + (rp - 2) * 2);
        int row0 = m0 + base;
        if (row0 < N_NODES) {
            #pragma unroll
            for (int cg = 0; cg < 4; cg++) {
                float2 v = make_float2(lo32(acc[rp][2 * cg]), lo32(acc[rp][2 * cg + 1]));
                *(float2*)&g_y[(size_t)row0 * D + cg * 32 + tx * 2] = v;
            }
        }
        if (row0 + 1 < N_NODES) {
            #pragma unroll
            for (int cg = 0; cg < 4; cg++) {
                float2 v = make_float2(hi32(acc[rp][2 * cg]), hi32(acc[rp][2 * cg + 1]));
                *(float2*)&g_y[(size_t)(row0 + 1) * D + cg * 32 + tx * 2] = v;
            }
        }
    }
}

// ---------------- nodes -> hyperedges gather (warp per edge) ----------------
__global__ void k_edge_gather() {
    int w = (blockIdx.x * blockDim.x + threadIdx.x) >> 5;
    int lane = threadIdx.x & 31;
    if (w >= N_EDGES) return;
    int s = g_off_e[w], t = g_off_e[w + 1];
    float4 acc = make_float4(0.f, 0.f, 0.f, 0.f);
    for (int base = s; base < t; base += 32) {
        int rem = t - base;
        int n = (lane < rem) ? g_csr_e[base + lane] : 0;
        int cnt = rem < 32 ? rem : 32;
        for (int j = 0; j < cnt; j++) {
            int nn = __shfl_sync(0xffffffffu, n, j);
            float4 v = *(const float4*)&g_y[(size_t)nn * D + lane * 4];
            acc.x += v.x; acc.y += v.y; acc.z += v.z; acc.w += v.w;
        }
    }
    float bi = g_binv[w];
    acc.x *= bi; acc.y *= bi; acc.z *= bi; acc.w *= bi;
    *(float4*)&g_ef[(size_t)w * D + lane * 4] = acc;
}

// ---------------- hyperedges -> nodes gather + bias (+relu) ----------------
__global__ void k_node_gather(float* __restrict__ outp,
                              const float* __restrict__ b, int doRelu) {
    int w = (blockIdx.x * blockDim.x + threadIdx.x) >> 5;
    int lane = threadIdx.x & 31;
    if (w >= N_NODES) return;
    float* out = outp ? outp : g_h;
    int s = g_off_n[w], t = g_off_n[w + 1];
    float4 acc = make_float4(0.f, 0.f, 0.f, 0.f);
    for (int base = s; base < t; base += 32) {
        int rem = t - base;
        int e = (lane < rem) ? g_csr_n[base + lane] : 0;
        int cnt = rem < 32 ? rem : 32;
        for (int j = 0; j < cnt; j++) {
            int ee = __shfl_sync(0xffffffffu, e, j);
            float4 v = *(const float4*)&g_ef[(size_t)ee * D + lane * 4];
            acc.x += v.x; acc.y += v.y; acc.z += v.z; acc.w += v.w;
        }
    }
    float di = g_dinv[w];
    float4 bv = ((const float4*)b)[lane];
    float4 r;
    r.x = acc.x * di + bv.x;
    r.y = acc.y * di + bv.y;
    r.z = acc.z * di + bv.z;
    r.w = acc.w * di + bv.w;
    if (doRelu) {
        r.x = fmaxf(r.x, 0.f); r.y = fmaxf(r.y, 0.f);
        r.z = fmaxf(r.z, 0.f); r.w = fmaxf(r.w, 0.f);
    }
    *(float4*)&out[(size_t)w * D + lane * 4] = r;
}

// ---------------- attr passthrough ----------------
__global__ void k_copy_attr(const float4* __restrict__ in, float4* __restrict__ out) {
    int i = blockIdx.x * blockDim.x + threadIdx.x;
    if (i < ATTR_FLOATS / 4) out[i] = in[i];
}

// ---------------- launch ----------------
extern "C" void kernel_launch(void* const* d_in, const int* in_sizes, int n_in,
                              void* d_out, int out_size) {
    const float* x        = (const float*)d_in[0];
    const int*   node_idx = (const int*)  d_in[1];
    const int*   edge_idx = (const int*)  d_in[2];
    const float* attr     = (const float*)d_in[3];
    const float* W1 = (const float*)d_in[4];
    const float* b1 = (const float*)d_in[5];
    const float* W2 = (const float*)d_in[6];
    const float* b2 = (const float*)d_in[7];
    const float* W3 = (const float*)d_in[8];
    const float* b3 = (const float*)d_in[9];
    float* out = (float*)d_out;

    // CSR build (once; reused by all 3 layers)
    k_zero <<<(N_NODES + 255) / 256, 256>>>();
    k_count<<<(N_INC   + 255) / 256, 256>>>(node_idx, edge_idx);

    int nb_e = (N_EDGES + 1023) / 1024;   // 25
    int nb_n = (N_NODES + 1023) / 1024;   // 98
    k_scan1<<<nb_e, 1024>>>(0, N_EDGES);
    k_scan2<<<1, 1024>>>(nb_e);
    k_scan3<<<nb_e, 1024>>>(0, N_EDGES);
    k_scan1<<<nb_n, 1024>>>(1, N_NODES);
    k_scan2<<<1, 1024>>>(nb_n);
    k_scan3<<<nb_n, 1024>>>(1, N_NODES);

    k_inv <<<(N_NODES + 255) / 256, 256>>>();
    k_fill<<<(N_INC   + 255) / 256, 256>>>(node_idx, edge_idx);

    const int gemm_grid = (N_NODES + 127) / 128;        // 782
    const int eg_grid   = (N_EDGES * 32 + 255) / 256;   // 3125
    const int ng_grid   = (N_NODES * 32 + 255) / 256;   // 12500

    // Layer 1
    k_gemm<<<gemm_grid, 256>>>(x, W1);
    k_edge_gather<<<eg_grid, 256>>>();
    k_node_gather<<<ng_grid, 256>>>(nullptr, b1, 1);
    // Layer 2
    k_gemm<<<gemm_grid, 256>>>(nullptr, W2);
    k_edge_gather<<<eg_grid, 256>>>();
    k_node_gather<<<ng_grid, 256>>>(nullptr, b2, 1);
    // Layer 3 (no relu, straight into output)
    k_gemm<<<gemm_grid, 256>>>(nullptr, W3);
    k_edge_gather<<<eg_grid, 256>>>();
    k_node_gather<<<ng_grid, 256>>>(out, b3, 0);

    // hyperedge_attr passthrough after h
    k_copy_attr<<<(ATTR_FLOATS / 4 + 255) / 256, 256>>>(
        (const float4*)attr, (float4*)(out + (size_t)N_NODES * D));
}

// round 5
// speedup vs baseline: 3.2908x; 1.7554x over previous
#include <cuda_runtime.h>
#include <cstdint>

#define N_NODES 100000
#define N_EDGES 25000
#define N_INC   600000
#define D       128
#define ATTR_FLOATS (25000*32)
#define NB_E 25     // ceil(25000/1024)
#define NB_N 98     // ceil(100000/1024)

typedef unsigned long long ull;

// ---------------- scratch (no allocations; zero-init at load, cleanup
// kernel restores zeros at the end of every execution) ----------------
__device__ float g_h  [N_NODES*D];    // node features between layers
__device__ float g_es [N_EDGES*D];    // edge aggregate (Binv * sum of node feats)
__device__ float g_ef2[N_EDGES*D];    // edge aggregate @ W
__device__ int   g_cnt_e[N_EDGES];
__device__ int   g_cnt_n[N_NODES];
__device__ int   g_off_e[N_EDGES+1];
__device__ int   g_off_n[N_NODES+1];
__device__ int   g_cur_e[N_EDGES];
__device__ int   g_cur_n[N_NODES];
__device__ int   g_csr_e[N_INC];      // node ids grouped by edge
__device__ int   g_csr_n[N_INC];      // edge ids grouped by node
__device__ float g_binv[N_EDGES];
__device__ float g_dinv[N_NODES];
__device__ int   g_bsums[160];        // [0..24]=edge blocks, [32..129]=node blocks

// ---------------- helpers ----------------
__device__ __forceinline__ void ffma2(ull &d, ull a, ull b) {
    asm("fma.rn.f32x2 %0, %1, %2, %0;" : "+l"(d) : "l"(a), "l"(b));
}
__device__ __forceinline__ ull dupf(float f) {
    unsigned u = __float_as_uint(f);
    return ((ull)u << 32) | (ull)u;
}
__device__ __forceinline__ float lo32(ull v) { return __uint_as_float((unsigned)v); }
__device__ __forceinline__ float hi32(ull v) { return __uint_as_float((unsigned)(v >> 32)); }

__device__ __forceinline__ int blockScanInc(int v, int* ws) {
    int lane = threadIdx.x & 31, wid = threadIdx.x >> 5;
    #pragma unroll
    for (int o = 1; o < 32; o <<= 1) {
        int n = __shfl_up_sync(0xffffffffu, v, o);
        if (lane >= o) v += n;
    }
    if (lane == 31) ws[wid] = v;
    __syncthreads();
    if (wid == 0) {
        int nw = blockDim.x >> 5;
        int s = (lane < nw) ? ws[lane] : 0;
        #pragma unroll
        for (int o = 1; o < 32; o <<= 1) {
            int n = __shfl_up_sync(0xffffffffu, s, o);
            if (lane >= o) s += n;
        }
        ws[lane] = s;
    }
    __syncthreads();
    if (wid > 0) v += ws[wid - 1];
    return v;
}

// ---------------- CSR build ----------------
// counters are zero on entry (zero-init at load + k_cleanup at end of run)
__global__ void k_count(const int* __restrict__ ni, const int* __restrict__ ei) {
    int i = blockIdx.x * blockDim.x + threadIdx.x;
    if (i < N_INC) {
        atomicAdd(&g_cnt_e[ei[i]], 1);
        atomicAdd(&g_cnt_n[ni[i]], 1);
    }
}

// per-block exclusive scan of both count arrays (blocks [0,NB_E) = edges,
// [NB_E, NB_E+NB_N) = nodes)
__global__ void k_scan_all() {
    __shared__ int ws[32];
    int b = blockIdx.x;
    if (b < NB_E) {
        int i = b * 1024 + threadIdx.x;
        int v = (i < N_EDGES) ? g_cnt_e[i] : 0;
        int inc = blockScanInc(v, ws);
        if (i < N_EDGES) g_off_e[i] = inc - v;
        if (threadIdx.x == 1023) g_bsums[b] = inc;
    } else {
        int bb = b - NB_E;
        int i = bb * 1024 + threadIdx.x;
        int v = (i < N_NODES) ? g_cnt_n[i] : 0;
        int inc = blockScanInc(v, ws);
        if (i < N_NODES) g_off_n[i] = inc - v;
        if (threadIdx.x == 1023) g_bsums[32 + bb] = inc;
    }
}

// scan the block sums of both arrays in one block
__global__ void k_scan_mid() {
    __shared__ int ws[32];
    int tid = threadIdx.x;
    int v = (tid < NB_E) ? g_bsums[tid] : 0;
    int inc = blockScanInc(v, ws);
    if (tid < NB_E) g_bsums[tid] = inc - v;   // exclusive
    __syncthreads();
    int v2 = (tid < NB_N) ? g_bsums[32 + tid] : 0;
    int inc2 = blockScanInc(v2, ws);
    if (tid < NB_N) g_bsums[32 + tid] = inc2 - v2;
}

// add block bases, sentinel ends, inverse degrees
__global__ void k_finish() {
    int b = blockIdx.x;
    if (b < NB_E) {
        int i = b * 1024 + threadIdx.x;
        if (i < N_EDGES) {
            g_off_e[i] += g_bsums[b];
            int c = g_cnt_e[i];
            g_binv[i] = (c > 0) ? (1.0f / (float)c) : 0.0f;
        }
        if (b == 0 && threadIdx.x == 0) {
            g_off_e[N_EDGES] = N_INC;
            g_off_n[N_NODES] = N_INC;
        }
    } else {
        int i = (b - NB_E) * 1024 + threadIdx.x;
        if (i < N_NODES) {
            g_off_n[i] += g_bsums[32 + b - NB_E];
            int c = g_cnt_n[i];
            g_dinv[i] = (c > 0) ? (1.0f / (float)c) : 0.0f;
        }
    }
}

__global__ void k_fill(const int* __restrict__ ni, const int* __restrict__ ei) {
    int i = blockIdx.x * blockDim.x + threadIdx.x;
    if (i < N_INC) {
        int e = ei[i], n = ni[i];
        int pe = atomicAdd(&g_cur_e[e], 1);
        g_csr_e[g_off_e[e] + pe] = n;
        int pn = atomicAdd(&g_cur_n[n], 1);
        g_csr_n[g_off_n[n] + pn] = e;
    }
}

// restore counters to zero for the next execution of the sequence
__global__ void k_cleanup() {
    int i = blockIdx.x * blockDim.x + threadIdx.x;
    if (i < N_EDGES) { g_cnt_e[i] = 0; g_cur_e[i] = 0; }
    if (i < N_NODES) { g_cnt_n[i] = 0; g_cur_n[i] = 0; }
}

// ---------------- GEMM: C[nrows x 128] = A @ W  (fp32 via f32x2) -----------
// 128x128 tile, 256 threads, thread tile 8 rows x 8 cols, row-pair f32x2
// accumulators, conflict-free LDS (see round-2 notes).
__global__ void __launch_bounds__(256, 2)
k_gemm(const float* __restrict__ A, float* __restrict__ C,
       const float* __restrict__ W, int nrows) {
    __shared__ float As[2][8][128];     // k-major: As[kk][m]
    __shared__ ull   Bs[2][8][128];     // dup'd:   Bs[kk][n] = (w,w)

    const int tid = threadIdx.x;
    const int m0  = blockIdx.x * 128;
    const int tx = tid & 15, ty = tid >> 4;
    const int lr = tid >> 1;            // 0..127  A-tile load row
    const int lc = (tid & 1) * 4;       // 0/4     A-tile load k offset
    const int bk = tid >> 5;            // 0..7    B-tile load k
    const int bn = (tid & 31) * 4;      // 0..124  B-tile load n

    ull acc[4][8];
    #pragma unroll
    for (int r = 0; r < 4; r++)
        #pragma unroll
        for (int j = 0; j < 8; j++) acc[r][j] = 0ull;

    auto loadStage = [&](int k0, int buf) {
        float4 av = make_float4(0.f, 0.f, 0.f, 0.f);
        int row = m0 + lr;
        if (row < nrows)
            av = *(const float4*)&A[(size_t)row * D + k0 + lc];
        As[buf][lc + 0][lr] = av.x;
        As[buf][lc + 1][lr] = av.y;
        As[buf][lc + 2][lr] = av.z;
        As[buf][lc + 3][lr] = av.w;
        float4 wv = *(const float4*)&W[(size_t)(k0 + bk) * D + bn];
        Bs[buf][bk][bn + 0] = dupf(wv.x);
        Bs[buf][bk][bn + 1] = dupf(wv.y);
        Bs[buf][bk][bn + 2] = dupf(wv.z);
        Bs[buf][bk][bn + 3] = dupf(wv.w);
    };

    loadStage(0, 0);
    __syncthreads();

    for (int k0 = 0; k0 < 128; k0 += 8) {
        int buf = (k0 >> 3) & 1;
        if (k0 + 8 < 128) loadStage(k0 + 8, buf ^ 1);
        #pragma unroll
        for (int kk = 0; kk < 8; kk++) {
            ulonglong2 a0 = *(const ulonglong2*)&As[buf][kk][ty * 4];
            ulonglong2 a1 = *(const ulonglong2*)&As[buf][kk][64 + ty * 4];
            ull a[4] = { a0.x, a0.y, a1.x, a1.y };
            ulonglong2 b0 = *(const ulonglong2*)&Bs[buf][kk][      tx * 2];
            ulonglong2 b1 = *(const ulonglong2*)&Bs[buf][kk][32  + tx * 2];
            ulonglong2 b2 = *(const ulonglong2*)&Bs[buf][kk][64  + tx * 2];
            ulonglong2 b3 = *(const ulonglong2*)&Bs[buf][kk][96  + tx * 2];
            ull b[8] = { b0.x, b0.y, b1.x, b1.y, b2.x, b2.y, b3.x, b3.y };
            #pragma unroll
            for (int r = 0; r < 4; r++)
                #pragma unroll
                for (int j = 0; j < 8; j++)
                    ffma2(acc[r][j], a[r], b[j]);
        }
        __syncthreads();
    }

    #pragma unroll
    for (int rp = 0; rp < 4; rp++) {
        int base = (rp < 2) ? (ty * 4 + rp * 2) : (64 + ty * 4 + (rp - 2) * 2);
        int row0 = m0 + base;
        if (row0 < nrows) {
            #pragma unroll
            for (int cg = 0; cg < 4; cg++) {
                float2 v = make_float2(lo32(acc[rp][2 * cg]), lo32(acc[rp][2 * cg + 1]));
                *(float2*)&C[(size_t)row0 * D + cg * 32 + tx * 2] = v;
            }
        }
        if (row0 + 1 < nrows) {
            #pragma unroll
            for (int cg = 0; cg < 4; cg++) {
                float2 v = make_float2(hi32(acc[rp][2 * cg]), hi32(acc[rp][2 * cg + 1]));
                *(float2*)&C[(size_t)(row0 + 1) * D + cg * 32 + tx * 2] = v;
            }
        }
    }
}

// ---------------- nodes -> hyperedges gather: g_es = Binv * H^T in ---------
__global__ void k_edge_gather(const float* __restrict__ in) {
    int w = (blockIdx.x * blockDim.x + threadIdx.x) >> 5;
    int lane = threadIdx.x & 31;
    if (w >= N_EDGES) return;
    int s = g_off_e[w], t = g_off_e[w + 1];
    float4 acc = make_float4(0.f, 0.f, 0.f, 0.f);
    #pragma unroll 4
    for (int j = s; j < t; j++) {
        int nn = __ldg(&g_csr_e[j]);                 // uniform across warp
        float4 v = *(const float4*)&in[(size_t)nn * D + lane * 4];
        acc.x += v.x; acc.y += v.y; acc.z += v.z; acc.w += v.w;
    }
    float bi = g_binv[w];
    acc.x *= bi; acc.y *= bi; acc.z *= bi; acc.w *= bi;
    *(float4*)&g_es[(size_t)w * D + lane * 4] = acc;
}

// ---------------- hyperedges -> nodes gather + bias (+relu) ----------------
__global__ void k_node_gather(float* __restrict__ out,
                              const float* __restrict__ b, int doRelu) {
    int w = (blockIdx.x * blockDim.x + threadIdx.x) >> 5;
    int lane = threadIdx.x & 31;
    if (w >= N_NODES) return;
    int s = g_off_n[w], t = g_off_n[w + 1];
    float4 acc = make_float4(0.f, 0.f, 0.f, 0.f);
    #pragma unroll 4
    for (int j = s; j < t; j++) {
        int ee = __ldg(&g_csr_n[j]);                 // uniform across warp
        float4 v = *(const float4*)&g_ef2[(size_t)ee * D + lane * 4];
        acc.x += v.x; acc.y += v.y; acc.z += v.z; acc.w += v.w;
    }
    float di = g_dinv[w];
    float4 bv = ((const float4*)b)[lane];
    float4 r;
    r.x = acc.x * di + bv.x;
    r.y = acc.y * di + bv.y;
    r.z = acc.z * di + bv.z;
    r.w = acc.w * di + bv.w;
    if (doRelu) {
        r.x = fmaxf(r.x, 0.f); r.y = fmaxf(r.y, 0.f);
        r.z = fmaxf(r.z, 0.f); r.w = fmaxf(r.w, 0.f);
    }
    *(float4*)&out[(size_t)w * D + lane * 4] = r;
}

// ---------------- attr passthrough ----------------
__global__ void k_copy_attr(const float4* __restrict__ in, float4* __restrict__ out) {
    int i = blockIdx.x * blockDim.x + threadIdx.x;
    if (i < ATTR_FLOATS / 4) out[i] = in[i];
}

// ---------------- launch ----------------
extern "C" void kernel_launch(void* const* d_in, const int* in_sizes, int n_in,
                              void* d_out, int out_size) {
    const float* x        = (const float*)d_in[0];
    const int*   node_idx = (const int*)  d_in[1];
    const int*   edge_idx = (const int*)  d_in[2];
    const float* attr     = (const float*)d_in[3];
    const float* W1 = (const float*)d_in[4];
    const float* b1 = (const float*)d_in[5];
    const float* W2 = (const float*)d_in[6];
    const float* b2 = (const float*)d_in[7];
    const float* W3 = (const float*)d_in[8];
    const float* b3 = (const float*)d_in[9];
    float* out = (float*)d_out;

    float *p_h, *p_es, *p_ef2;
    cudaGetSymbolAddress((void**)&p_h,   g_h);
    cudaGetSymbolAddress((void**)&p_es,  g_es);
    cudaGetSymbolAddress((void**)&p_ef2, g_ef2);

    const int gemm_grid = (N_EDGES + 127) / 128;        // 196
    const int eg_grid   = (N_EDGES * 32 + 255) / 256;   // 3125
    const int ng_grid   = (N_NODES * 32 + 255) / 256;   // 12500
    const int scan_grid = NB_E + NB_N;                  // 123

    // CSR build: 5 launches (counters pre-zeroed; see k_cleanup)
    k_count   <<<(N_INC + 255) / 256, 256>>>(node_idx, edge_idx);   // 0
    k_scan_all<<<scan_grid, 1024>>>();                              // 1
    k_scan_mid<<<1, 1024>>>();                                      // 2
    k_finish  <<<scan_grid, 1024>>>();                              // 3
    k_fill    <<<(N_INC + 255) / 256, 256>>>(node_idx, edge_idx);   // 4

    // Layer 1  (launch #5 = edge_gather -> ncu -s 5 target)
    k_edge_gather<<<eg_grid, 256>>>(x);                             // 5
    k_gemm<<<gemm_grid, 256>>>(p_es, p_ef2, W1, N_EDGES);           // 6
    k_node_gather<<<ng_grid, 256>>>(p_h, b1, 1);                    // 7
    // Layer 2
    k_edge_gather<<<eg_grid, 256>>>(p_h);
    k_gemm<<<gemm_grid, 256>>>(p_es, p_ef2, W2, N_EDGES);
    k_node_gather<<<ng_grid, 256>>>(p_h, b2, 1);
    // Layer 3 (no relu, straight into output)
    k_edge_gather<<<eg_grid, 256>>>(p_h);
    k_gemm<<<gemm_grid, 256>>>(p_es, p_ef2, W3, N_EDGES);
    k_node_gather<<<ng_grid, 256>>>(out, b3, 0);

    // hyperedge_attr passthrough
    k_copy_attr<<<(ATTR_FLOATS / 4 + 255) / 256, 256>>>(
        (const float4*)attr, (float4*)(out + (size_t)N_NODES * D));

    // restore counters to zero for the next execution
    k_cleanup<<<(N_NODES + 255) / 256, 256>>>();
}

// round 6
// speedup vs baseline: 3.9732x; 1.2074x over previous
#include <cuda_runtime.h>
#include <cuda_bf16.h>
#include <cstdint>

#define N_NODES 100000
#define N_EDGES 25000
#define N_INC   600000
#define D       128
#define ATTR_VEC4 (25000*32/4)
#define NB_E 25     // ceil(25000/1024)
#define NB_N 98     // ceil(100000/1024)

typedef unsigned long long ull;

// ---------------- scratch (no allocations; zero-init at load, cleanup
// restores zeros at the end of every execution) ----------------
__device__ float g_h  [N_NODES*D];    // node features between layers
__device__ float g_es [N_EDGES*D];    // edge aggregate (Binv * sum node feats)
__device__ float g_ef2[N_EDGES*D];    // edge aggregate @ W
__device__ int   g_cnt_e[N_EDGES];
__device__ int   g_cnt_n[N_NODES];
__device__ int   g_off_e[N_EDGES+1];
__device__ int   g_off_n[N_NODES+1];
__device__ int   g_cur_e[N_EDGES];
__device__ int   g_cur_n[N_NODES];
__device__ int   g_csr_e[N_INC];      // node ids grouped by edge
__device__ int   g_csr_n[N_INC];      // edge ids grouped by node
__device__ float g_binv[N_EDGES];
__device__ float g_dinv[N_NODES];
__device__ int   g_bsums[160];

// ---------------- helpers ----------------
__device__ __forceinline__ uint32_t smem_u32(const void* p) {
    uint32_t a;
    asm("{ .reg .u64 t; cvta.to.shared.u64 t, %1; cvt.u32.u64 %0, t; }"
        : "=r"(a) : "l"(p));
    return a;
}
__device__ __forceinline__ void ldsm4(uint32_t* r, uint32_t addr) {
    asm volatile("ldmatrix.sync.aligned.m8n8.x4.shared.b16 {%0,%1,%2,%3}, [%4];"
                 : "=r"(r[0]), "=r"(r[1]), "=r"(r[2]), "=r"(r[3]) : "r"(addr));
}
__device__ __forceinline__ void ldsm2t(uint32_t* r, uint32_t addr) {
    asm volatile("ldmatrix.sync.aligned.m8n8.x2.trans.shared.b16 {%0,%1}, [%2];"
                 : "=r"(r[0]), "=r"(r[1]) : "r"(addr));
}
__device__ __forceinline__ void mma16816(float* c, const uint32_t* a,
                                         const uint32_t* b) {
    asm volatile(
        "mma.sync.aligned.m16n8k16.row.col.f32.bf16.bf16.f32 "
        "{%0,%1,%2,%3}, {%4,%5,%6,%7}, {%8,%9}, {%0,%1,%2,%3};"
        : "+f"(c[0]), "+f"(c[1]), "+f"(c[2]), "+f"(c[3])
        : "r"(a[0]), "r"(a[1]), "r"(a[2]), "r"(a[3]), "r"(b[0]), "r"(b[1]));
}

__device__ __forceinline__ int blockScanInc(int v, int* ws) {
    int lane = threadIdx.x & 31, wid = threadIdx.x >> 5;
    #pragma unroll
    for (int o = 1; o < 32; o <<= 1) {
        int n = __shfl_up_sync(0xffffffffu, v, o);
        if (lane >= o) v += n;
    }
    if (lane == 31) ws[wid] = v;
    __syncthreads();
    if (wid == 0) {
        int nw = blockDim.x >> 5;
        int s = (lane < nw) ? ws[lane] : 0;
        #pragma unroll
        for (int o = 1; o < 32; o <<= 1) {
            int n = __shfl_up_sync(0xffffffffu, s, o);
            if (lane >= o) s += n;
        }
        ws[lane] = s;
    }
    __syncthreads();
    if (wid > 0) v += ws[wid - 1];
    return v;
}

// ---------------- CSR build (counters zero on entry) ----------------
__global__ void k_count(const int* __restrict__ ni, const int* __restrict__ ei) {
    int i = blockIdx.x * blockDim.x + threadIdx.x;
    if (i < N_INC) {
        atomicAdd(&g_cnt_e[ei[i]], 1);
        atomicAdd(&g_cnt_n[ni[i]], 1);
    }
}

__global__ void k_scan_all() {
    __shared__ int ws[32];
    int b = blockIdx.x;
    if (b < NB_E) {
        int i = b * 1024 + threadIdx.x;
        int v = (i < N_EDGES) ? g_cnt_e[i] : 0;
        int inc = blockScanInc(v, ws);
        if (i < N_EDGES) g_off_e[i] = inc - v;
        if (threadIdx.x == 1023) g_bsums[b] = inc;
    } else {
        int bb = b - NB_E;
        int i = bb * 1024 + threadIdx.x;
        int v = (i < N_NODES) ? g_cnt_n[i] : 0;
        int inc = blockScanInc(v, ws);
        if (i < N_NODES) g_off_n[i] = inc - v;
        if (threadIdx.x == 1023) g_bsums[32 + bb] = inc;
    }
}

__global__ void k_scan_mid() {
    __shared__ int ws[32];
    int tid = threadIdx.x;
    int v = (tid < NB_E) ? g_bsums[tid] : 0;
    int inc = blockScanInc(v, ws);
    if (tid < NB_E) g_bsums[tid] = inc - v;
    __syncthreads();
    int v2 = (tid < NB_N) ? g_bsums[32 + tid] : 0;
    int inc2 = blockScanInc(v2, ws);
    if (tid < NB_N) g_bsums[32 + tid] = inc2 - v2;
}

__global__ void k_finish() {
    int b = blockIdx.x;
    if (b < NB_E) {
        int i = b * 1024 + threadIdx.x;
        if (i < N_EDGES) {
            g_off_e[i] += g_bsums[b];
            int c = g_cnt_e[i];
            g_binv[i] = (c > 0) ? (1.0f / (float)c) : 0.0f;
        }
        if (b == 0 && threadIdx.x == 0) {
            g_off_e[N_EDGES] = N_INC;
            g_off_n[N_NODES] = N_INC;
        }
    } else {
        int i = (b - NB_E) * 1024 + threadIdx.x;
        if (i < N_NODES) {
            g_off_n[i] += g_bsums[32 + b - NB_E];
            int c = g_cnt_n[i];
            g_dinv[i] = (c > 0) ? (1.0f / (float)c) : 0.0f;
        }
    }
}

__global__ void k_fill(const int* __restrict__ ni, const int* __restrict__ ei) {
    int i = blockIdx.x * blockDim.x + threadIdx.x;
    if (i < N_INC) {
        int e = ei[i], n = ni[i];
        int pe = atomicAdd(&g_cur_e[e], 1);
        g_csr_e[g_off_e[e] + pe] = n;
        int pn = atomicAdd(&g_cur_n[n], 1);
        g_csr_n[g_off_n[n] + pn] = e;
    }
}

// ---------------- GEMM via HMMA: C[nrows x 128] = A @ W  -------------------
// bf16-split (A=Ah+Al, W=Wh+Wl; acc AhWh+AlWh+AhWl in fp32 fragments).
// 128x128 CTA tile, 256 threads = 8 warps; warp w owns rows 16w..16w+15.
// K processed in 4 chunks of 32. smem padded: A stride 40 bf16, B stride 136.
#define A_STR 40
#define B_STR 136

__global__ void __launch_bounds__(256, 2)
k_gemm_mma(const float* __restrict__ A, float* __restrict__ C,
           const float* __restrict__ W, int nrows) {
    __shared__ __nv_bfloat16 sAh[128 * A_STR];
    __shared__ __nv_bfloat16 sAl[128 * A_STR];
    __shared__ __nv_bfloat16 sBh[32 * B_STR];
    __shared__ __nv_bfloat16 sBl[32 * B_STR];

    const int tid  = threadIdx.x;
    const int wid  = tid >> 5, lane = tid & 31;
    const int m0   = blockIdx.x * 128;
    const int r0   = wid * 16;

    const uint32_t ah_b = smem_u32(sAh);
    const uint32_t al_b = smem_u32(sAl);
    const uint32_t bh_b = smem_u32(sBh);
    const uint32_t bl_b = smem_u32(sBl);

    // ldmatrix lane->address row/col pieces
    const int a_lr = (lane & 7) + ((lane & 8) ? 8 : 0);   // row within 16
    const int a_lc = (lane & 16) ? 8 : 0;                 // k offset within 16
    const int b_lr = (lane & 7) + (((lane >> 3) & 1) ? 8 : 0); // k row within 16

    float acc[16][4];
    #pragma unroll
    for (int t = 0; t < 16; t++)
        #pragma unroll
        for (int j = 0; j < 4; j++) acc[t][j] = 0.f;

    // load indices: A chunk 128 rows x 32 k; thread t: row=t>>1, kq=(t&1)*16
    const int lrow = tid >> 1, lkq = (tid & 1) * 16;
    // W chunk 32 k x 128 n; thread t: kr=t>>3, nq=(t&7)*16
    const int lkr = tid >> 3, lnq = (tid & 7) * 16;

    for (int kc = 0; kc < 128; kc += 32) {
        // ---- load + split chunk ----
        {
            int grow = m0 + lrow;
            const float4* ap = (grow < nrows)
                ? (const float4*)&A[(size_t)grow * D + kc + lkq] : nullptr;
            #pragma unroll
            for (int q = 0; q < 4; q++) {
                float4 v = ap ? ap[q] : make_float4(0.f, 0.f, 0.f, 0.f);
                float f[4] = { v.x, v.y, v.z, v.w };
                #pragma unroll
                for (int u = 0; u < 2; u++) {
                    __nv_bfloat16 h0 = __float2bfloat16(f[2*u]);
                    __nv_bfloat16 h1 = __float2bfloat16(f[2*u+1]);
                    __nv_bfloat16 l0 = __float2bfloat16(f[2*u]   - __bfloat162float(h0));
                    __nv_bfloat16 l1 = __float2bfloat16(f[2*u+1] - __bfloat162float(h1));
                    int k = lkq + q * 4 + u * 2;
                    *(__nv_bfloat162*)&sAh[lrow * A_STR + k] = __nv_bfloat162(h0, h1);
                    *(__nv_bfloat162*)&sAl[lrow * A_STR + k] = __nv_bfloat162(l0, l1);
                }
            }
            const float4* wp = (const float4*)&W[(size_t)(kc + lkr) * D + lnq];
            #pragma unroll
            for (int q = 0; q < 4; q++) {
                float4 v = wp[q];
                float f[4] = { v.x, v.y, v.z, v.w };
                #pragma unroll
                for (int u = 0; u < 2; u++) {
                    __nv_bfloat16 h0 = __float2bfloat16(f[2*u]);
                    __nv_bfloat16 h1 = __float2bfloat16(f[2*u+1]);
                    __nv_bfloat16 l0 = __float2bfloat16(f[2*u]   - __bfloat162float(h0));
                    __nv_bfloat16 l1 = __float2bfloat16(f[2*u+1] - __bfloat162float(h1));
                    int n = lnq + q * 4 + u * 2;
                    *(__nv_bfloat162*)&sBh[lkr * B_STR + n] = __nv_bfloat162(h0, h1);
                    *(__nv_bfloat162*)&sBl[lkr * B_STR + n] = __nv_bfloat162(l0, l1);
                }
            }
        }
        __syncthreads();

        // ---- compute: two k16 steps ----
        #pragma unroll
        for (int ks = 0; ks < 32; ks += 16) {
            uint32_t ah[4], al[4];
            uint32_t aoff = (uint32_t)((r0 + a_lr) * A_STR + ks + a_lc) * 2;
            ldsm4(ah, ah_b + aoff);
            ldsm4(al, al_b + aoff);
            #pragma unroll
            for (int nt = 0; nt < 16; nt++) {
                uint32_t bh[2], bl[2];
                uint32_t boff = (uint32_t)((ks + b_lr) * B_STR + nt * 8) * 2;
                ldsm2t(bh, bh_b + boff);
                ldsm2t(bl, bl_b + boff);
                mma16816(acc[nt], ah, bh);
                mma16816(acc[nt], al, bh);
                mma16816(acc[nt], ah, bl);
            }
        }
        __syncthreads();
    }

    // ---- epilogue ----
    const int grp = lane >> 2, tig = lane & 3;
    int row0 = m0 + r0 + grp;
    int row1 = row0 + 8;
    #pragma unroll
    for (int nt = 0; nt < 16; nt++) {
        int col = nt * 8 + tig * 2;
        if (row0 < nrows)
            *(float2*)&C[(size_t)row0 * D + col] = make_float2(acc[nt][0], acc[nt][1]);
        if (row1 < nrows)
            *(float2*)&C[(size_t)row1 * D + col] = make_float2(acc[nt][2], acc[nt][3]);
    }
}

// ---------------- nodes -> hyperedges gather: g_es = Binv * H^T in ---------
__global__ void k_edge_gather(const float* __restrict__ in) {
    int w = (blockIdx.x * blockDim.x + threadIdx.x) >> 5;
    int lane = threadIdx.x & 31;
    if (w >= N_EDGES) return;
    int s = g_off_e[w], t = g_off_e[w + 1];
    float4 acc = make_float4(0.f, 0.f, 0.f, 0.f);
    #pragma unroll 4
    for (int j = s; j < t; j++) {
        int nn = __ldg(&g_csr_e[j]);
        float4 v = *(const float4*)&in[(size_t)nn * D + lane * 4];
        acc.x += v.x; acc.y += v.y; acc.z += v.z; acc.w += v.w;
    }
    float bi = g_binv[w];
    acc.x *= bi; acc.y *= bi; acc.z *= bi; acc.w *= bi;
    *(float4*)&g_es[(size_t)w * D + lane * 4] = acc;
}

// ---------------- hyperedges -> nodes gather + bias (+relu) ----------------
__global__ void k_node_gather(float* __restrict__ out,
                              const float* __restrict__ b, int doRelu) {
    int w = (blockIdx.x * blockDim.x + threadIdx.x) >> 5;
    int lane = threadIdx.x & 31;
    if (w >= N_NODES) return;
    int s = g_off_n[w], t = g_off_n[w + 1];
    float4 acc = make_float4(0.f, 0.f, 0.f, 0.f);
    #pragma unroll 4
    for (int j = s; j < t; j++) {
        int ee = __ldg(&g_csr_n[j]);
        float4 v = *(const float4*)&g_ef2[(size_t)ee * D + lane * 4];
        acc.x += v.x; acc.y += v.y; acc.z += v.z; acc.w += v.w;
    }
    float di = g_dinv[w];
    float4 bv = ((const float4*)b)[lane];
    float4 r;
    r.x = acc.x * di + bv.x;
    r.y = acc.y * di + bv.y;
    r.z = acc.z * di + bv.z;
    r.w = acc.w * di + bv.w;
    if (doRelu) {
        r.x = fmaxf(r.x, 0.f); r.y = fmaxf(r.y, 0.f);
        r.z = fmaxf(r.z, 0.f); r.w = fmaxf(r.w, 0.f);
    }
    *(float4*)&out[(size_t)w * D + lane * 4] = r;
}

// ---------------- attr passthrough + counter cleanup (fused) ----------------
__global__ void k_attr_cleanup(const float4* __restrict__ in,
                               float4* __restrict__ out) {
    int i = blockIdx.x * blockDim.x + threadIdx.x;
    if (i < ATTR_VEC4) out[i] = in[i];
    if (i < N_EDGES) { g_cnt_e[i] = 0; g_cur_e[i] = 0; }
    if (i < N_NODES) { g_cnt_n[i] = 0; g_cur_n[i] = 0; }
}

// ---------------- launch ----------------
extern "C" void kernel_launch(void* const* d_in, const int* in_sizes, int n_in,
                              void* d_out, int out_size) {
    const float* x        = (const float*)d_in[0];
    const int*   node_idx = (const int*)  d_in[1];
    const int*   edge_idx = (const int*)  d_in[2];
    const float* attr     = (const float*)d_in[3];
    const float* W1 = (const float*)d_in[4];
    const float* b1 = (const float*)d_in[5];
    const float* W2 = (const float*)d_in[6];
    const float* b2 = (const float*)d_in[7];
    const float* W3 = (const float*)d_in[8];
    const float* b3 = (const float*)d_in[9];
    float* out = (float*)d_out;

    float *p_h, *p_es, *p_ef2;
    cudaGetSymbolAddress((void**)&p_h,   g_h);
    cudaGetSymbolAddress((void**)&p_es,  g_es);
    cudaGetSymbolAddress((void**)&p_ef2, g_ef2);

    const int gemm_grid = (N_EDGES + 127) / 128;        // 196
    const int eg_grid   = (N_EDGES * 32 + 255) / 256;   // 3125
    const int ng_grid   = (N_NODES * 32 + 255) / 256;   // 12500
    const int scan_grid = NB_E + NB_N;                  // 123

    // CSR build
    k_count   <<<(N_INC + 255) / 256, 256>>>(node_idx, edge_idx);   // 0
    k_scan_all<<<scan_grid, 1024>>>();                              // 1
    k_scan_mid<<<1, 1024>>>();                                      // 2
    k_finish  <<<scan_grid, 1024>>>();                              // 3
    k_fill    <<<(N_INC + 255) / 256, 256>>>(node_idx, edge_idx);   // 4

    // Layer 1
    k_edge_gather<<<eg_grid, 256>>>(x);                             // 5
    k_gemm_mma<<<gemm_grid, 256>>>(p_es, p_ef2, W1, N_EDGES);       // 6
    k_node_gather<<<ng_grid, 256>>>(p_h, b1, 1);                    // 7
    // Layer 2
    k_edge_gather<<<eg_grid, 256>>>(p_h);
    k_gemm_mma<<<gemm_grid, 256>>>(p_es, p_ef2, W2, N_EDGES);
    k_node_gather<<<ng_grid, 256>>>(p_h, b2, 1);
    // Layer 3 (no relu, straight into output)
    k_edge_gather<<<eg_grid, 256>>>(p_h);
    k_gemm_mma<<<gemm_grid, 256>>>(p_es, p_ef2, W3, N_EDGES);
    k_node_gather<<<ng_grid, 256>>>(out, b3, 0);

    // attr passthrough + restore counters for next execution
    k_attr_cleanup<<<(ATTR_VEC4 + 255) / 256, 256>>>(
        (const float4*)attr, (float4*)(out + (size_t)N_NODES * D));
}